// round 13
// baseline (speedup 1.0000x reference)
#include <cuda_runtime.h>
#include <cuda_bf16.h>
#include <math.h>
#include <stdint.h>

#define SEQ    2048
#define DMODEL 2048
#define NHEAD  32
#define NKV    8
#define HDIM   64
#define NEXP   8
#define FDIM   7168
#define NTOK   2048
#define NSLOT  4096
#define EPSF   1e-5f

typedef __nv_bfloat16 bf16;

// ---------------- device scratch ----------------
__device__ bf16  g_hn_hi[NTOK * DMODEL], g_hn_lo[NTOK * DMODEL];
__device__ float g_q[NTOK * NHEAD * HDIM], g_k[NTOK * NKV * HDIM], g_v[NTOK * NKV * HDIM];
__device__ bf16  g_at_hi[NTOK * DMODEL], g_at_lo[NTOK * DMODEL];
__device__ float g_h2[NTOK * DMODEL], g_tn[NTOK * DMODEL];
__device__ bf16  g_tn_hi[NTOK * DMODEL], g_tn_lo[NTOK * DMODEL];
__device__ int   g_topi[NTOK * 2];
__device__ float g_topw[NTOK * 2];
__device__ int   g_slot_token[NSLOT], g_slot_of[NTOK * 2], g_off[NEXP + 1];
__device__ float g_gate[(size_t)NSLOT * FDIM], g_up[(size_t)NSLOT * FDIM];
__device__ bf16  g_act_hi[(size_t)NSLOT * FDIM], g_act_lo[(size_t)NSLOT * FDIM];
__device__ float g_down[(size_t)NSLOT * DMODEL];

// ---------------- helpers ----------------
__device__ __forceinline__ uint32_t smem_u32(const void* p) {
    uint32_t a;
    asm("{ .reg .u64 t; cvta.to.shared.u64 t, %1; cvt.u32.u64 %0, t; }" : "=r"(a) : "l"(p));
    return a;
}
__device__ __forceinline__ void ldsm4(uint32_t* r, uint32_t addr) {
    asm volatile("ldmatrix.sync.aligned.m8n8.x4.shared.b16 {%0,%1,%2,%3}, [%4];"
                 : "=r"(r[0]), "=r"(r[1]), "=r"(r[2]), "=r"(r[3]) : "r"(addr));
}
__device__ __forceinline__ void mma16816(float* c, const uint32_t* a, const uint32_t* b) {
    asm volatile(
        "mma.sync.aligned.m16n8k16.row.col.f32.bf16.bf16.f32 "
        "{%0,%1,%2,%3}, {%4,%5,%6,%7}, {%8,%9}, {%0,%1,%2,%3};"
        : "+f"(c[0]), "+f"(c[1]), "+f"(c[2]), "+f"(c[3])
        : "r"(a[0]), "r"(a[1]), "r"(a[2]), "r"(a[3]), "r"(b[0]), "r"(b[1]));
}
__device__ __forceinline__ void cp16(uint32_t dst, const void* src) {
    asm volatile("cp.async.cg.shared.global [%0], [%1], 16;" :: "r"(dst), "l"(src));
}
__device__ __forceinline__ void cp_commit() { asm volatile("cp.async.commit_group;"); }
__device__ __forceinline__ void cp_wait0()  { asm volatile("cp.async.wait_group 0;"); }
__device__ __forceinline__ void bfsplit(float x, bf16& h, bf16& l) {
    h = __float2bfloat16_rn(x);
    l = __float2bfloat16_rn(x - __bfloat162float(h));
}
__device__ __forceinline__ uint32_t packbf(bf16 a, bf16 b) {
    return (uint32_t)*(unsigned short*)&a | ((uint32_t)*(unsigned short*)&b << 16);
}

// ---------------- GEMM geometry: BM=128, BN=64, KC=32, 256 thr, 3 CTAs/SM ----------------
#define BM 128
#define BN 64
#define KC 32
#define ASTR 40
#define BSTR 40
#define OFF_AH(b) (512u + (b) * 20480u)
#define OFF_AL(b) (512u + 10240u + (b) * 20480u)
#define OFF_BH(b) (41472u + (b) * 10240u)
#define OFF_BL(b) (41472u + 5120u + (b) * 10240u)
#define GEMM_SMEM 61952

__device__ __forceinline__ void gemm_issueA(uint32_t sb, int buf,
    const bf16* __restrict__ Ahi, const bf16* __restrict__ Alo,
    const int* rowg, int K, int k0, int tid)
{
#pragma unroll
    for (int it = 0; it < 2; it++) {
        int idx = tid + it * 256;          // 0..511
        int row = idx >> 2, seg = idx & 3;
        size_t goff = (size_t)rowg[row] * K + k0 + seg * 8;
        uint32_t soff = ((uint32_t)row * ASTR + (uint32_t)seg * 8) * 2u;
        cp16(sb + OFF_AH(buf) + soff, Ahi + goff);
        cp16(sb + OFF_AL(buf) + soff, Alo + goff);
    }
}
__device__ __forceinline__ void gemm_ldgB(const float* __restrict__ Bp, int N, int k0,
                                          int n0, int bn, int bk, float* bst)
{
    const float* p = Bp + (size_t)(k0 + bk) * N + n0 + bn;
#pragma unroll
    for (int j = 0; j < 8; j++) bst[j] = p[(size_t)j * N];
}
__device__ __forceinline__ void gemm_stsB(char* sm, int buf, int bn, int bk, const float* bst)
{
    uint32_t h[4], l[4];
#pragma unroll
    for (int j = 0; j < 4; j++) {
        bf16 h0, l0, h1, l1;
        bfsplit(bst[2 * j], h0, l0);
        bfsplit(bst[2 * j + 1], h1, l1);
        h[j] = packbf(h0, h1);
        l[j] = packbf(l0, l1);
    }
    uint32_t off = ((uint32_t)bn * BSTR + (uint32_t)bk) * 2u;
    *(uint4*)(sm + OFF_BH(buf) + off) = make_uint4(h[0], h[1], h[2], h[3]);
    *(uint4*)(sm + OFF_BL(buf) + off) = make_uint4(l[0], l[1], l[2], l[3]);
}
// compute: B fragments via ldmatrix (4 tiles = nf0klo, nf0khi, nf1klo, nf1khi)
__device__ __forceinline__ void gemm_compute(uint32_t sb, char* sm, int buf,
                                             int wm, int wn, int lane, float acc[4][2][4])
{
    uint32_t ah_s = sb + OFF_AH(buf), al_s = sb + OFF_AL(buf);
    uint32_t bh_s = sb + OFF_BH(buf), bl_s = sb + OFF_BL(buf);
    int grp = lane >> 3, lrow = lane & 7;
    uint32_t brow = (uint32_t)(wn * 16 + (grp >> 1) * 8 + lrow) * (BSTR * 2u) + (uint32_t)(grp & 1) * 16u;
#pragma unroll
    for (int kf = 0; kf < 2; kf++) {
        uint32_t bh[4], bl[4];
        ldsm4(bh, bh_s + brow + (uint32_t)kf * 32u);
        ldsm4(bl, bl_s + brow + (uint32_t)kf * 32u);
#pragma unroll
        for (int mf = 0; mf < 4; mf++) {
            int r = wm * 64 + mf * 16 + (lane & 15);
            uint32_t boff = ((uint32_t)r * ASTR + (uint32_t)(kf * 16 + (lane >> 4) * 8)) * 2u;
            uint32_t ah[4], al[4];
            ldsm4(ah, ah_s + boff);
            ldsm4(al, al_s + boff);
            mma16816(acc[mf][0], ah, bh + 0);
            mma16816(acc[mf][0], ah, bl + 0);
            mma16816(acc[mf][0], al, bh + 0);
            mma16816(acc[mf][1], ah, bh + 2);
            mma16816(acc[mf][1], ah, bl + 2);
            mma16816(acc[mf][1], al, bh + 2);
        }
    }
}

// ======================= standard HMMA GEMM =======================
__global__ __launch_bounds__(256, 3) void tc_gemm(
    const bf16* __restrict__ Ahi, const bf16* __restrict__ Alo,
    const float* __restrict__ B, float* __restrict__ C, const float* __restrict__ res,
    int M, int N, int K, int grouped, int gather)
{
    int e = blockIdx.z;
    int rbeg = 0, rows = M;
    if (grouped) { rbeg = g_off[e]; rows = g_off[e + 1] - rbeg; }
    int mg0 = blockIdx.y * BM;
    if (mg0 >= rows) return;
    int n0 = blockIdx.x * BN;
    const float* Bp = B + (size_t)e * K * N;

    extern __shared__ char sm[];
    uint32_t sb = smem_u32(sm);
    int* rowg = (int*)sm;
    int tid = threadIdx.x, lane = tid & 31, warp = tid >> 5;
    int wm = warp >> 2, wn = warp & 3;

    for (int r = tid; r < BM; r += 256) {
        int m = mg0 + r, rg;
        if (gather)       rg = (m < rows) ? g_slot_token[rbeg + m] : 0;
        else if (grouped) rg = (m < rows) ? (rbeg + m) : rbeg;
        else              rg = (m < rows) ? m : 0;
        rowg[r] = rg;
    }
    __syncthreads();

    float acc[4][2][4];
#pragma unroll
    for (int a = 0; a < 4; a++)
#pragma unroll
        for (int b = 0; b < 2; b++)
#pragma unroll
            for (int c = 0; c < 4; c++) acc[a][b][c] = 0.f;

    int bn = tid & 63, bk = (tid >> 6) * 8;
    float bst[8];
    int NC = K / KC;

    gemm_issueA(sb, 0, Ahi, Alo, rowg, K, 0, tid);
    cp_commit();
    gemm_ldgB(Bp, N, 0, n0, bn, bk, bst);
    cp_wait0();
    __syncthreads();
    gemm_stsB(sm, 0, bn, bk, bst);
    __syncthreads();

    for (int ch = 0; ch < NC; ch++) {
        int buf = ch & 1;
        if (ch + 1 < NC) {
            gemm_issueA(sb, buf ^ 1, Ahi, Alo, rowg, K, (ch + 1) * KC, tid);
            cp_commit();
            gemm_ldgB(Bp, N, (ch + 1) * KC, n0, bn, bk, bst);
        }
        gemm_compute(sb, sm, buf, wm, wn, lane, acc);
        if (ch + 1 < NC) {
            cp_wait0();
            __syncthreads();
            gemm_stsB(sm, buf ^ 1, bn, bk, bst);
            __syncthreads();
        }
    }

#pragma unroll
    for (int mf = 0; mf < 4; mf++) {
#pragma unroll
        for (int half = 0; half < 2; half++) {
            int m = mg0 + wm * 64 + mf * 16 + (lane >> 2) + half * 8;
            if (m < rows) {
                size_t crow = (size_t)(rbeg + m);
                float* cp = C + crow * N + n0 + wn * 16 + (lane & 3) * 2;
                const float* rp = res ? res + (size_t)m * N + n0 + wn * 16 + (lane & 3) * 2 : nullptr;
#pragma unroll
                for (int nf = 0; nf < 2; nf++) {
                    float2 v;
                    v.x = acc[mf][nf][half * 2];
                    v.y = acc[mf][nf][half * 2 + 1];
                    if (rp) { v.x += rp[nf * 8]; v.y += rp[nf * 8 + 1]; }
                    *(float2*)(cp + nf * 8) = v;
                }
            }
        }
    }
}

// ======================= merged K+V projection GEMM =======================
// grid (16, 16): blockIdx.x < 8 -> Wk cols x*64 -> g_k; else Wv cols (x-8)*64 -> g_v.
__global__ __launch_bounds__(256, 3) void tc_gemm_kv(
    const bf16* __restrict__ Ahi, const bf16* __restrict__ Alo,
    const float* __restrict__ Wk, const float* __restrict__ Wv)
{
    int sel = blockIdx.x >> 3;
    int n0 = (blockIdx.x & 7) * BN;
    const float* Bp = sel ? Wv : Wk;
    float* C = sel ? g_v : g_k;
    const int N = 512, K = DMODEL;
    int mg0 = blockIdx.y * BM;

    extern __shared__ char sm[];
    uint32_t sb = smem_u32(sm);
    int* rowg = (int*)sm;
    int tid = threadIdx.x, lane = tid & 31, warp = tid >> 5;
    int wm = warp >> 2, wn = warp & 3;

    for (int r = tid; r < BM; r += 256) rowg[r] = mg0 + r;
    __syncthreads();

    float acc[4][2][4];
#pragma unroll
    for (int a = 0; a < 4; a++)
#pragma unroll
        for (int b = 0; b < 2; b++)
#pragma unroll
            for (int c = 0; c < 4; c++) acc[a][b][c] = 0.f;

    int bn = tid & 63, bk = (tid >> 6) * 8;
    float bst[8];
    int NC = K / KC;

    gemm_issueA(sb, 0, Ahi, Alo, rowg, K, 0, tid);
    cp_commit();
    gemm_ldgB(Bp, N, 0, n0, bn, bk, bst);
    cp_wait0();
    __syncthreads();
    gemm_stsB(sm, 0, bn, bk, bst);
    __syncthreads();

    for (int ch = 0; ch < NC; ch++) {
        int buf = ch & 1;
        if (ch + 1 < NC) {
            gemm_issueA(sb, buf ^ 1, Ahi, Alo, rowg, K, (ch + 1) * KC, tid);
            cp_commit();
            gemm_ldgB(Bp, N, (ch + 1) * KC, n0, bn, bk, bst);
        }
        gemm_compute(sb, sm, buf, wm, wn, lane, acc);
        if (ch + 1 < NC) {
            cp_wait0();
            __syncthreads();
            gemm_stsB(sm, buf ^ 1, bn, bk, bst);
            __syncthreads();
        }
    }

#pragma unroll
    for (int mf = 0; mf < 4; mf++) {
#pragma unroll
        for (int half = 0; half < 2; half++) {
            int m = mg0 + wm * 64 + mf * 16 + (lane >> 2) + half * 8;
            float* cp = C + (size_t)m * N + n0 + wn * 16 + (lane & 3) * 2;
#pragma unroll
            for (int nf = 0; nf < 2; nf++) {
                float2 v;
                v.x = acc[mf][nf][half * 2];
                v.y = acc[mf][nf][half * 2 + 1];
                *(float2*)(cp + nf * 8) = v;
            }
        }
    }
}

// ======================= small kernels =======================
__global__ __launch_bounds__(256) void rmsnorm_kernel(
    const float* __restrict__ x, const float* __restrict__ w,
    float* __restrict__ yf, bf16* __restrict__ yh, bf16* __restrict__ yl)
{
    int row = blockIdx.x;
    const float* xr = x + (size_t)row * DMODEL;
    __shared__ float red[256];
    float ss = 0.f;
    const float4* x4 = (const float4*)xr;
    for (int i = threadIdx.x; i < DMODEL / 4; i += 256) {
        float4 v = x4[i];
        ss += v.x * v.x + v.y * v.y + v.z * v.z + v.w * v.w;
    }
    red[threadIdx.x] = ss;
    __syncthreads();
    for (int s = 128; s > 0; s >>= 1) {
        if (threadIdx.x < s) red[threadIdx.x] += red[threadIdx.x + s];
        __syncthreads();
    }
    float inv = rsqrtf(red[0] / (float)DMODEL + EPSF);
    for (int i = threadIdx.x; i < DMODEL; i += 256) {
        float val = xr[i] * inv * w[i];
        if (yf) yf[(size_t)row * DMODEL + i] = val;
        bf16 h, l;
        bfsplit(val, h, l);
        yh[(size_t)row * DMODEL + i] = h;
        yl[(size_t)row * DMODEL + i] = l;
    }
}

__global__ void rope_kernel(float* __restrict__ x, const int* __restrict__ pos, int nheads)
{
    int s = blockIdx.x, h = blockIdx.y, i = threadIdx.x;
    float p = (float)pos[s];
    float inv = expf(-((float)(2 * i) / 64.f) * 13.815510557964274f);
    float ang = p * inv;
    float sn, cs;
    sincosf(ang, &sn, &cs);
    float* xp = x + ((size_t)s * nheads + h) * HDIM;
    float x1 = xp[i], x2 = xp[i + 32];
    xp[i]      = x1 * cs - x2 * sn;
    xp[i + 32] = x2 * cs + x1 * sn;
}

// ---------------- flash attention: 2-way dim split, q-tile 32 ----------------
__global__ __launch_bounds__(256, 3) void flash_kernel()
{
    int bq = gridDim.x - 1 - blockIdx.x;
    int kvh = blockIdx.y;
    int tid = threadIdx.x;
    int w = tid >> 5, l = tid & 31;
    int half = l >> 4;
    int unit = w * 16 + (l & 15);
    int ql = unit & 31, sub = unit >> 5;
    int qpos = bq * 32 + ql;
    int qh = kvh * 4 + sub;
    __shared__ __align__(16) float Ks[32][64];
    __shared__ __align__(16) float Vs[32][64];
    float qreg[32], o[32];
    const float4* qp = (const float4*)(g_q + ((size_t)qpos * NHEAD + qh) * HDIM + half * 32);
#pragma unroll
    for (int d4 = 0; d4 < 8; d4++) {
        float4 v = qp[d4];
        qreg[4 * d4] = v.x * 0.125f; qreg[4 * d4 + 1] = v.y * 0.125f;
        qreg[4 * d4 + 2] = v.z * 0.125f; qreg[4 * d4 + 3] = v.w * 0.125f;
        o[4 * d4] = 0.f; o[4 * d4 + 1] = 0.f; o[4 * d4 + 2] = 0.f; o[4 * d4 + 3] = 0.f;
    }
    float m = -INFINITY, lsum = 0.f;
    int kend = bq * 32 + 32;
    int qmax_w = bq * 32 + (w & 1) * 16 + 15;
    for (int kt = 0; kt < kend; kt += 32) {
        for (int i = tid; i < 32 * 16; i += 256) {
            int j = i >> 4, d4 = (i & 15) * 4;
            *(float4*)&Ks[j][d4] = *(const float4*)(g_k + ((size_t)(kt + j) * NKV + kvh) * HDIM + d4);
            *(float4*)&Vs[j][d4] = *(const float4*)(g_v + ((size_t)(kt + j) * NKV + kvh) * HDIM + d4);
        }
        __syncthreads();
        int jw = qmax_w - kt + 1;
        if (jw > 32) jw = 32;
        for (int j = 0; j < jw; j += 4) {
            float s0 = 0.f, s1 = 0.f, s2 = 0.f, s3 = 0.f;
            int hb = half * 32;
#pragma unroll
            for (int d = 0; d < 32; d += 4) {
                float4 k0 = *(const float4*)&Ks[j][hb + d];
                float4 k1 = *(const float4*)&Ks[j + 1][hb + d];
                float4 k2 = *(const float4*)&Ks[j + 2][hb + d];
                float4 k3 = *(const float4*)&Ks[j + 3][hb + d];
                s0 += qreg[d] * k0.x + qreg[d + 1] * k0.y + qreg[d + 2] * k0.z + qreg[d + 3] * k0.w;
                s1 += qreg[d] * k1.x + qreg[d + 1] * k1.y + qreg[d + 2] * k1.z + qreg[d + 3] * k1.w;
                s2 += qreg[d] * k2.x + qreg[d + 1] * k2.y + qreg[d + 2] * k2.z + qreg[d + 3] * k2.w;
                s3 += qreg[d] * k3.x + qreg[d + 1] * k3.y + qreg[d + 2] * k3.z + qreg[d + 3] * k3.w;
            }
            s0 += __shfl_xor_sync(0xFFFFFFFFu, s0, 16);
            s1 += __shfl_xor_sync(0xFFFFFFFFu, s1, 16);
            s2 += __shfl_xor_sync(0xFFFFFFFFu, s2, 16);
            s3 += __shfl_xor_sync(0xFFFFFFFFu, s3, 16);
            if (kt + j     > qpos) s0 = -1e30f;
            if (kt + j + 1 > qpos) s1 = -1e30f;
            if (kt + j + 2 > qpos) s2 = -1e30f;
            if (kt + j + 3 > qpos) s3 = -1e30f;
            float mn = fmaxf(fmaxf(fmaxf(s0, s1), fmaxf(s2, s3)), m);
            float corr = __expf(m - mn);
            float p0 = __expf(s0 - mn), p1 = __expf(s1 - mn);
            float p2 = __expf(s2 - mn), p3 = __expf(s3 - mn);
            lsum = lsum * corr + p0 + p1 + p2 + p3;
            m = mn;
#pragma unroll
            for (int d = 0; d < 32; d += 4) {
                float4 v0 = *(const float4*)&Vs[j][hb + d];
                float4 v1 = *(const float4*)&Vs[j + 1][hb + d];
                float4 v2 = *(const float4*)&Vs[j + 2][hb + d];
                float4 v3 = *(const float4*)&Vs[j + 3][hb + d];
                o[d]     = o[d]     * corr + p0 * v0.x + p1 * v1.x + p2 * v2.x + p3 * v3.x;
                o[d + 1] = o[d + 1] * corr + p0 * v0.y + p1 * v1.y + p2 * v2.y + p3 * v3.y;
                o[d + 2] = o[d + 2] * corr + p0 * v0.z + p1 * v1.z + p2 * v2.z + p3 * v3.z;
                o[d + 3] = o[d + 3] * corr + p0 * v0.w + p1 * v1.w + p2 * v2.w + p3 * v3.w;
            }
        }
        __syncthreads();
    }
    float invl = 1.f / lsum;
    size_t base = (size_t)qpos * DMODEL + (size_t)qh * HDIM + half * 32;
#pragma unroll
    for (int d = 0; d < 32; d++) {
        float val = o[d] * invl;
        bf16 h, lo;
        bfsplit(val, h, lo);
        g_at_hi[base + d] = h;
        g_at_lo[base + d] = lo;
    }
}

__global__ __launch_bounds__(128) void router_kernel(
    const float* __restrict__ T, const float* __restrict__ Wr)
{
    int t = blockIdx.x;
    __shared__ float sred[128 * 8];
    float acc[8] = {};
    const float* tr = T + (size_t)t * DMODEL;
    for (int d = threadIdx.x; d < DMODEL; d += 128) {
        float x = tr[d];
        const float* wr = Wr + (size_t)d * NEXP;
#pragma unroll
        for (int e = 0; e < 8; e++) acc[e] += x * wr[e];
    }
#pragma unroll
    for (int e = 0; e < 8; e++) sred[threadIdx.x * 8 + e] = acc[e];
    __syncthreads();
    for (int s = 64; s > 0; s >>= 1) {
        if (threadIdx.x < s) {
#pragma unroll
            for (int e = 0; e < 8; e++)
                sred[threadIdx.x * 8 + e] += sred[(threadIdx.x + s) * 8 + e];
        }
        __syncthreads();
    }
    if (threadIdx.x == 0) {
        float best = -1e30f, second = -1e30f;
        int bi = 0, si = 0;
#pragma unroll
        for (int e = 0; e < 8; e++) {
            float v = sred[e];
            if (v > best)        { second = best; si = bi; best = v; bi = e; }
            else if (v > second) { second = v; si = e; }
        }
        float p0 = 1.f / (1.f + expf(second - best));
        g_topi[2 * t] = bi;  g_topi[2 * t + 1] = si;
        g_topw[2 * t] = p0;  g_topw[2 * t + 1] = 1.f - p0;
    }
}

__global__ __launch_bounds__(256) void assign_kernel()
{
    __shared__ int cnt[NEXP], base[NEXP + 1], cur[NEXP];
    if (threadIdx.x < NEXP) cnt[threadIdx.x] = 0;
    __syncthreads();
    for (int t = threadIdx.x; t < NTOK; t += 256) {
        atomicAdd(&cnt[g_topi[2 * t]], 1);
        atomicAdd(&cnt[g_topi[2 * t + 1]], 1);
    }
    __syncthreads();
    if (threadIdx.x == 0) {
        int s = 0;
        for (int e = 0; e < NEXP; e++) { base[e] = s; s += cnt[e]; }
        base[NEXP] = s;
    }
    __syncthreads();
    if (threadIdx.x < NEXP) cur[threadIdx.x] = base[threadIdx.x];
    if (threadIdx.x < NEXP + 1) g_off[threadIdx.x] = base[threadIdx.x];
    __syncthreads();
    for (int t = threadIdx.x; t < NTOK; t += 256) {
#pragma unroll
        for (int k = 0; k < 2; k++) {
            int e = g_topi[2 * t + k];
            int slot = atomicAdd(&cur[e], 1);
            g_slot_token[slot] = t;
            g_slot_of[2 * t + k] = slot;
        }
    }
}

__global__ __launch_bounds__(512) void silu_kernel()
{
    size_t i = ((size_t)blockIdx.x * 512 + threadIdx.x) * 4;
    float4 g = *(const float4*)(g_gate + i);
    float4 u = *(const float4*)(g_up + i);
    float a0 = g.x / (1.f + __expf(-g.x)) * u.x;
    float a1 = g.y / (1.f + __expf(-g.y)) * u.y;
    float a2 = g.z / (1.f + __expf(-g.z)) * u.z;
    float a3 = g.w / (1.f + __expf(-g.w)) * u.w;
    bf16 h0, l0, h1, l1, h2, l2, h3, l3;
    bfsplit(a0, h0, l0); bfsplit(a1, h1, l1);
    bfsplit(a2, h2, l2); bfsplit(a3, h3, l3);
    bf16* ph = g_act_hi + i;
    bf16* pl = g_act_lo + i;
    ph[0] = h0; ph[1] = h1; ph[2] = h2; ph[3] = h3;
    pl[0] = l0; pl[1] = l1; pl[2] = l2; pl[3] = l3;
}

__global__ __launch_bounds__(256) void combine_kernel(
    const float* __restrict__ h2, float* __restrict__ out)
{
    int t = blockIdx.x;
    int s0 = g_slot_of[2 * t], s1 = g_slot_of[2 * t + 1];
    float w0 = g_topw[2 * t], w1 = g_topw[2 * t + 1];
    const float* d0 = g_down + (size_t)s0 * DMODEL;
    const float* d1 = g_down + (size_t)s1 * DMODEL;
    const float* hr = h2 + (size_t)t * DMODEL;
    float* orow = out + (size_t)t * DMODEL;
    for (int d = threadIdx.x; d < DMODEL; d += 256)
        orow[d] = hr[d] + w0 * d0[d] + w1 * d1[d];
}

// ======================= launch =======================
extern "C" void kernel_launch(void* const* d_in, const int* in_sizes, int n_in,
                              void* d_out, int out_size)
{
    const float* hs   = (const float*)d_in[0];
    const int*   pos  = (const int*)d_in[1];
    const float* ln1w = (const float*)d_in[2];
    const float* Wq   = (const float*)d_in[3];
    const float* Wk   = (const float*)d_in[4];
    const float* Wv   = (const float*)d_in[5];
    const float* Wo   = (const float*)d_in[6];
    const float* ln2w = (const float*)d_in[7];
    const float* Wr   = (const float*)d_in[8];
    const float* W1   = (const float*)d_in[9];
    const float* W3   = (const float*)d_in[10];
    const float* W2   = (const float*)d_in[11];
    float* out = (float*)d_out;

    cudaFuncSetAttribute(tc_gemm, cudaFuncAttributeMaxDynamicSharedMemorySize, GEMM_SMEM);
    cudaFuncSetAttribute(tc_gemm_kv, cudaFuncAttributeMaxDynamicSharedMemorySize, GEMM_SMEM);

    void* p;
    cudaGetSymbolAddress(&p, g_hn_hi);  bf16* hn_hi = (bf16*)p;
    cudaGetSymbolAddress(&p, g_hn_lo);  bf16* hn_lo = (bf16*)p;
    cudaGetSymbolAddress(&p, g_q);      float* q    = (float*)p;
    cudaGetSymbolAddress(&p, g_k);      float* k    = (float*)p;
    cudaGetSymbolAddress(&p, g_v);      float* v    = (float*)p;
    cudaGetSymbolAddress(&p, g_at_hi);  bf16* at_hi = (bf16*)p;
    cudaGetSymbolAddress(&p, g_at_lo);  bf16* at_lo = (bf16*)p;
    cudaGetSymbolAddress(&p, g_h2);     float* h2   = (float*)p;
    cudaGetSymbolAddress(&p, g_tn);     float* tn   = (float*)p;
    cudaGetSymbolAddress(&p, g_tn_hi);  bf16* tn_hi = (bf16*)p;
    cudaGetSymbolAddress(&p, g_tn_lo);  bf16* tn_lo = (bf16*)p;
    cudaGetSymbolAddress(&p, g_gate);   float* gate = (float*)p;
    cudaGetSymbolAddress(&p, g_up);     float* up   = (float*)p;
    cudaGetSymbolAddress(&p, g_act_hi); bf16* ac_hi = (bf16*)p;
    cudaGetSymbolAddress(&p, g_act_lo); bf16* ac_lo = (bf16*)p;
    cudaGetSymbolAddress(&p, g_down);   float* down = (float*)p;

    // 1. rmsnorm1 -> bf16 hi/lo
    rmsnorm_kernel<<<NTOK, 256>>>(hs, ln1w, nullptr, hn_hi, hn_lo);
    // 2. Q projection + merged K/V projection
    tc_gemm<<<dim3(32, 16, 1), 256, GEMM_SMEM>>>(hn_hi, hn_lo, Wq, q, nullptr, NTOK, 2048, DMODEL, 0, 0);
    tc_gemm_kv<<<dim3(16, 16, 1), 256, GEMM_SMEM>>>(hn_hi, hn_lo, Wk, Wv);
    // 3. RoPE
    rope_kernel<<<dim3(SEQ, NHEAD), 32>>>(q, pos, NHEAD);
    rope_kernel<<<dim3(SEQ, NKV), 32>>>(k, pos, NKV);
    // 4. flash attention -> attn hi/lo
    flash_kernel<<<dim3(SEQ / 32, NKV), 256>>>();
    // 5. O projection + residual
    tc_gemm<<<dim3(32, 16, 1), 256, GEMM_SMEM>>>(at_hi, at_lo, Wo, h2, hs, NTOK, 2048, DMODEL, 0, 0);
    // 6. rmsnorm2
    rmsnorm_kernel<<<NTOK, 256>>>(h2, ln2w, tn, tn_hi, tn_lo);
    // 7-8. router + assignment
    router_kernel<<<NTOK, 128>>>(tn, Wr);
    assign_kernel<<<1, 256>>>();
    // 9. gate & up grouped GEMMs (gather)
    tc_gemm<<<dim3(112, 16, 8), 256, GEMM_SMEM>>>(tn_hi, tn_lo, W1, gate, nullptr, 0, FDIM, DMODEL, 1, 1);
    tc_gemm<<<dim3(112, 16, 8), 256, GEMM_SMEM>>>(tn_hi, tn_lo, W3, up, nullptr, 0, FDIM, DMODEL, 1, 1);
    // 10. silu(gate)*up -> act hi/lo
    silu_kernel<<<(int)((size_t)NSLOT * FDIM / 4 / 512), 512>>>();
    // 11. down grouped GEMM (slot-space A)
    tc_gemm<<<dim3(32, 16, 8), 256, GEMM_SMEM>>>(ac_hi, ac_lo, W2, down, nullptr, 0, DMODEL, FDIM, 1, 0);
    // 12. combine with residual
    combine_kernel<<<NTOK, 256>>>(h2, out);
}

// round 14
// speedup vs baseline: 1.5198x; 1.5198x over previous
#include <cuda_runtime.h>
#include <cuda_bf16.h>
#include <math.h>
#include <stdint.h>

#define SEQ    2048
#define DMODEL 2048
#define NHEAD  32
#define NKV    8
#define HDIM   64
#define NEXP   8
#define FDIM   7168
#define NTOK   2048
#define NSLOT  4096
#define EPSF   1e-5f

typedef __nv_bfloat16 bf16;

// ---------------- device scratch ----------------
__device__ bf16  g_hn_hi[NTOK * DMODEL], g_hn_lo[NTOK * DMODEL];
__device__ float g_q[NTOK * NHEAD * HDIM], g_k[NTOK * NKV * HDIM], g_v[NTOK * NKV * HDIM];
__device__ bf16  g_at_hi[NTOK * DMODEL], g_at_lo[NTOK * DMODEL];
__device__ float g_h2[NTOK * DMODEL], g_tn[NTOK * DMODEL];
__device__ bf16  g_tn_hi[NTOK * DMODEL], g_tn_lo[NTOK * DMODEL];
__device__ int   g_topi[NTOK * 2];
__device__ float g_topw[NTOK * 2];
__device__ int   g_slot_token[NSLOT], g_slot_of[NTOK * 2], g_off[NEXP + 1];
__device__ float g_gate[(size_t)NSLOT * FDIM], g_up[(size_t)NSLOT * FDIM];
__device__ bf16  g_act_hi[(size_t)NSLOT * FDIM], g_act_lo[(size_t)NSLOT * FDIM];
__device__ float g_down[(size_t)NSLOT * DMODEL];

// ---------------- helpers ----------------
__device__ __forceinline__ uint32_t smem_u32(const void* p) {
    uint32_t a;
    asm("{ .reg .u64 t; cvta.to.shared.u64 t, %1; cvt.u32.u64 %0, t; }" : "=r"(a) : "l"(p));
    return a;
}
__device__ __forceinline__ void ldsm4(uint32_t* r, uint32_t addr) {
    asm volatile("ldmatrix.sync.aligned.m8n8.x4.shared.b16 {%0,%1,%2,%3}, [%4];"
                 : "=r"(r[0]), "=r"(r[1]), "=r"(r[2]), "=r"(r[3]) : "r"(addr));
}
__device__ __forceinline__ void mma16816(float* c, const uint32_t* a, const uint32_t* b) {
    asm volatile(
        "mma.sync.aligned.m16n8k16.row.col.f32.bf16.bf16.f32 "
        "{%0,%1,%2,%3}, {%4,%5,%6,%7}, {%8,%9}, {%0,%1,%2,%3};"
        : "+f"(c[0]), "+f"(c[1]), "+f"(c[2]), "+f"(c[3])
        : "r"(a[0]), "r"(a[1]), "r"(a[2]), "r"(a[3]), "r"(b[0]), "r"(b[1]));
}
__device__ __forceinline__ void cp16(uint32_t dst, const void* src) {
    asm volatile("cp.async.cg.shared.global [%0], [%1], 16;" :: "r"(dst), "l"(src));
}
__device__ __forceinline__ void cp_commit() { asm volatile("cp.async.commit_group;"); }
__device__ __forceinline__ void cp_wait0()  { asm volatile("cp.async.wait_group 0;"); }
__device__ __forceinline__ void bfsplit(float x, bf16& h, bf16& l) {
    h = __float2bfloat16_rn(x);
    l = __float2bfloat16_rn(x - __bfloat162float(h));
}
__device__ __forceinline__ uint32_t packbf(bf16 a, bf16 b) {
    return (uint32_t)*(unsigned short*)&a | ((uint32_t)*(unsigned short*)&b << 16);
}

// ---------------- GEMM geometry: BM=128, BN=64, KC=32, 256 thr, 3 CTAs/SM ----------------
#define BM 128
#define BN 64
#define KC 32
#define ASTR 40
#define BSTR 40
#define OFF_AH(b) (512u + (b) * 20480u)
#define OFF_AL(b) (512u + 10240u + (b) * 20480u)
#define OFF_BH(b) (41472u + (b) * 10240u)
#define OFF_BL(b) (41472u + 5120u + (b) * 10240u)
#define GEMM_SMEM 61952

__device__ __forceinline__ void gemm_issueA(uint32_t sb, int buf,
    const bf16* __restrict__ Ahi, const bf16* __restrict__ Alo,
    const int* rowg, int K, int k0, int tid)
{
#pragma unroll
    for (int it = 0; it < 2; it++) {
        int idx = tid + it * 256;          // 0..511
        int row = idx >> 2, seg = idx & 3;
        size_t goff = (size_t)rowg[row] * K + k0 + seg * 8;
        uint32_t soff = ((uint32_t)row * ASTR + (uint32_t)seg * 8) * 2u;
        cp16(sb + OFF_AH(buf) + soff, Ahi + goff);
        cp16(sb + OFF_AL(buf) + soff, Alo + goff);
    }
}
__device__ __forceinline__ void gemm_ldgB(const float* __restrict__ Bp, int N, int k0,
                                          int n0, int bn, int bk, float* bst)
{
    const float* p = Bp + (size_t)(k0 + bk) * N + n0 + bn;
#pragma unroll
    for (int j = 0; j < 8; j++) bst[j] = p[(size_t)j * N];
}
__device__ __forceinline__ void gemm_stsB(char* sm, int buf, int bn, int bk, const float* bst)
{
    uint32_t h[4], l[4];
#pragma unroll
    for (int j = 0; j < 4; j++) {
        bf16 h0, l0, h1, l1;
        bfsplit(bst[2 * j], h0, l0);
        bfsplit(bst[2 * j + 1], h1, l1);
        h[j] = packbf(h0, h1);
        l[j] = packbf(l0, l1);
    }
    uint32_t off = ((uint32_t)bn * BSTR + (uint32_t)bk) * 2u;
    *(uint4*)(sm + OFF_BH(buf) + off) = make_uint4(h[0], h[1], h[2], h[3]);
    *(uint4*)(sm + OFF_BL(buf) + off) = make_uint4(l[0], l[1], l[2], l[3]);
}
// R10-proven compute loop: scalar B fragment loads (conflict-free), ldmatrix A only
__device__ __forceinline__ void gemm_compute(uint32_t sb, char* sm, int buf,
                                             int wm, int wn, int lane, float acc[4][2][4])
{
    bf16* Bh = (bf16*)(sm + OFF_BH(buf));
    bf16* Bl = (bf16*)(sm + OFF_BL(buf));
    uint32_t ah_s = sb + OFF_AH(buf), al_s = sb + OFF_AL(buf);
#pragma unroll
    for (int kf = 0; kf < 2; kf++) {
        uint32_t bh[2][2], bl[2][2];
        int kb = kf * 16 + (lane & 3) * 2;
#pragma unroll
        for (int nf = 0; nf < 2; nf++) {
            int n = wn * 16 + nf * 8 + (lane >> 2);
            bh[nf][0] = *(const uint32_t*)&Bh[n * BSTR + kb];
            bh[nf][1] = *(const uint32_t*)&Bh[n * BSTR + kb + 8];
            bl[nf][0] = *(const uint32_t*)&Bl[n * BSTR + kb];
            bl[nf][1] = *(const uint32_t*)&Bl[n * BSTR + kb + 8];
        }
#pragma unroll
        for (int mf = 0; mf < 4; mf++) {
            int r = wm * 64 + mf * 16 + (lane & 15);
            uint32_t boff = ((uint32_t)r * ASTR + (uint32_t)(kf * 16 + (lane >> 4) * 8)) * 2u;
            uint32_t ah[4], al[4];
            ldsm4(ah, ah_s + boff);
            ldsm4(al, al_s + boff);
#pragma unroll
            for (int nf = 0; nf < 2; nf++) {
                mma16816(acc[mf][nf], ah, bh[nf]);
                mma16816(acc[mf][nf], ah, bl[nf]);
                mma16816(acc[mf][nf], al, bh[nf]);
            }
        }
    }
}

// ======================= standard HMMA GEMM =======================
__global__ __launch_bounds__(256, 3) void tc_gemm(
    const bf16* __restrict__ Ahi, const bf16* __restrict__ Alo,
    const float* __restrict__ B, float* __restrict__ C, const float* __restrict__ res,
    int M, int N, int K, int grouped, int gather)
{
    int e = blockIdx.z;
    int rbeg = 0, rows = M;
    if (grouped) { rbeg = g_off[e]; rows = g_off[e + 1] - rbeg; }
    int mg0 = blockIdx.y * BM;
    if (mg0 >= rows) return;
    int n0 = blockIdx.x * BN;
    const float* Bp = B + (size_t)e * K * N;

    extern __shared__ char sm[];
    uint32_t sb = smem_u32(sm);
    int* rowg = (int*)sm;
    int tid = threadIdx.x, lane = tid & 31, warp = tid >> 5;
    int wm = warp >> 2, wn = warp & 3;

    for (int r = tid; r < BM; r += 256) {
        int m = mg0 + r, rg;
        if (gather)       rg = (m < rows) ? g_slot_token[rbeg + m] : 0;
        else if (grouped) rg = (m < rows) ? (rbeg + m) : rbeg;
        else              rg = (m < rows) ? m : 0;
        rowg[r] = rg;
    }
    __syncthreads();

    float acc[4][2][4];
#pragma unroll
    for (int a = 0; a < 4; a++)
#pragma unroll
        for (int b = 0; b < 2; b++)
#pragma unroll
            for (int c = 0; c < 4; c++) acc[a][b][c] = 0.f;

    int bn = tid & 63, bk = (tid >> 6) * 8;
    float bst[8];
    int NC = K / KC;

    gemm_issueA(sb, 0, Ahi, Alo, rowg, K, 0, tid);
    cp_commit();
    gemm_ldgB(Bp, N, 0, n0, bn, bk, bst);
    cp_wait0();
    __syncthreads();
    gemm_stsB(sm, 0, bn, bk, bst);
    __syncthreads();

    for (int ch = 0; ch < NC; ch++) {
        int buf = ch & 1;
        if (ch + 1 < NC) {
            gemm_issueA(sb, buf ^ 1, Ahi, Alo, rowg, K, (ch + 1) * KC, tid);
            cp_commit();
            gemm_ldgB(Bp, N, (ch + 1) * KC, n0, bn, bk, bst);
        }
        gemm_compute(sb, sm, buf, wm, wn, lane, acc);
        if (ch + 1 < NC) {
            cp_wait0();
            __syncthreads();
            gemm_stsB(sm, buf ^ 1, bn, bk, bst);
            __syncthreads();
        }
    }

#pragma unroll
    for (int mf = 0; mf < 4; mf++) {
#pragma unroll
        for (int half = 0; half < 2; half++) {
            int m = mg0 + wm * 64 + mf * 16 + (lane >> 2) + half * 8;
            if (m < rows) {
                size_t crow = (size_t)(rbeg + m);
                float* cp = C + crow * N + n0 + wn * 16 + (lane & 3) * 2;
                const float* rp = res ? res + (size_t)m * N + n0 + wn * 16 + (lane & 3) * 2 : nullptr;
#pragma unroll
                for (int nf = 0; nf < 2; nf++) {
                    float2 v;
                    v.x = acc[mf][nf][half * 2];
                    v.y = acc[mf][nf][half * 2 + 1];
                    if (rp) { v.x += rp[nf * 8]; v.y += rp[nf * 8 + 1]; }
                    *(float2*)(cp + nf * 8) = v;
                }
            }
        }
    }
}

// ======================= merged K+V projection GEMM =======================
// grid (16, 16): blockIdx.x < 8 -> Wk cols -> g_k; else Wv cols -> g_v.
__global__ __launch_bounds__(256, 3) void tc_gemm_kv(
    const bf16* __restrict__ Ahi, const bf16* __restrict__ Alo,
    const float* __restrict__ Wk, const float* __restrict__ Wv)
{
    int sel = blockIdx.x >> 3;
    int n0 = (blockIdx.x & 7) * BN;
    const float* Bp = sel ? Wv : Wk;
    float* C = sel ? g_v : g_k;
    const int N = 512, K = DMODEL;
    int mg0 = blockIdx.y * BM;

    extern __shared__ char sm[];
    uint32_t sb = smem_u32(sm);
    int* rowg = (int*)sm;
    int tid = threadIdx.x, lane = tid & 31, warp = tid >> 5;
    int wm = warp >> 2, wn = warp & 3;

    for (int r = tid; r < BM; r += 256) rowg[r] = mg0 + r;
    __syncthreads();

    float acc[4][2][4];
#pragma unroll
    for (int a = 0; a < 4; a++)
#pragma unroll
        for (int b = 0; b < 2; b++)
#pragma unroll
            for (int c = 0; c < 4; c++) acc[a][b][c] = 0.f;

    int bn = tid & 63, bk = (tid >> 6) * 8;
    float bst[8];
    int NC = K / KC;

    gemm_issueA(sb, 0, Ahi, Alo, rowg, K, 0, tid);
    cp_commit();
    gemm_ldgB(Bp, N, 0, n0, bn, bk, bst);
    cp_wait0();
    __syncthreads();
    gemm_stsB(sm, 0, bn, bk, bst);
    __syncthreads();

    for (int ch = 0; ch < NC; ch++) {
        int buf = ch & 1;
        if (ch + 1 < NC) {
            gemm_issueA(sb, buf ^ 1, Ahi, Alo, rowg, K, (ch + 1) * KC, tid);
            cp_commit();
            gemm_ldgB(Bp, N, (ch + 1) * KC, n0, bn, bk, bst);
        }
        gemm_compute(sb, sm, buf, wm, wn, lane, acc);
        if (ch + 1 < NC) {
            cp_wait0();
            __syncthreads();
            gemm_stsB(sm, buf ^ 1, bn, bk, bst);
            __syncthreads();
        }
    }

#pragma unroll
    for (int mf = 0; mf < 4; mf++) {
#pragma unroll
        for (int half = 0; half < 2; half++) {
            int m = mg0 + wm * 64 + mf * 16 + (lane >> 2) + half * 8;
            float* cp = C + (size_t)m * N + n0 + wn * 16 + (lane & 3) * 2;
#pragma unroll
            for (int nf = 0; nf < 2; nf++) {
                float2 v;
                v.x = acc[mf][nf][half * 2];
                v.y = acc[mf][nf][half * 2 + 1];
                *(float2*)(cp + nf * 8) = v;
            }
        }
    }
}

// ======================= small kernels =======================
__global__ __launch_bounds__(256) void rmsnorm_kernel(
    const float* __restrict__ x, const float* __restrict__ w,
    float* __restrict__ yf, bf16* __restrict__ yh, bf16* __restrict__ yl)
{
    int row = blockIdx.x;
    const float* xr = x + (size_t)row * DMODEL;
    __shared__ float red[256];
    float ss = 0.f;
    const float4* x4 = (const float4*)xr;
    for (int i = threadIdx.x; i < DMODEL / 4; i += 256) {
        float4 v = x4[i];
        ss += v.x * v.x + v.y * v.y + v.z * v.z + v.w * v.w;
    }
    red[threadIdx.x] = ss;
    __syncthreads();
    for (int s = 128; s > 0; s >>= 1) {
        if (threadIdx.x < s) red[threadIdx.x] += red[threadIdx.x + s];
        __syncthreads();
    }
    float inv = rsqrtf(red[0] / (float)DMODEL + EPSF);
    for (int i = threadIdx.x; i < DMODEL; i += 256) {
        float val = xr[i] * inv * w[i];
        if (yf) yf[(size_t)row * DMODEL + i] = val;
        bf16 h, l;
        bfsplit(val, h, l);
        yh[(size_t)row * DMODEL + i] = h;
        yl[(size_t)row * DMODEL + i] = l;
    }
}

// one block per position: 32 q heads + 8 k heads, 32 rotation pairs each = 1280 items
__global__ __launch_bounds__(256) void rope_all_kernel(const int* __restrict__ pos)
{
    int s = blockIdx.x;
    float p = (float)pos[s];
    for (int idx = threadIdx.x; idx < (NHEAD + NKV) * 32; idx += 256) {
        int h = idx >> 5, i = idx & 31;
        float inv = __expf(-((float)(2 * i) / 64.f) * 13.815510557964274f);
        float sn, cs;
        __sincosf(p * inv, &sn, &cs);
        float* xp;
        if (h < NHEAD) xp = g_q + ((size_t)s * NHEAD + h) * HDIM;
        else           xp = g_k + ((size_t)s * NKV + (h - NHEAD)) * HDIM;
        float x1 = xp[i], x2 = xp[i + 32];
        xp[i]      = x1 * cs - x2 * sn;
        xp[i + 32] = x2 * cs + x1 * sn;
    }
}

// ---------------- flash attention: 2-way dim split, q-tile 32 ----------------
__global__ __launch_bounds__(256, 3) void flash_kernel()
{
    int bq = gridDim.x - 1 - blockIdx.x;
    int kvh = blockIdx.y;
    int tid = threadIdx.x;
    int w = tid >> 5, l = tid & 31;
    int half = l >> 4;
    int unit = w * 16 + (l & 15);
    int ql = unit & 31, sub = unit >> 5;
    int qpos = bq * 32 + ql;
    int qh = kvh * 4 + sub;
    __shared__ __align__(16) float Ks[32][64];
    __shared__ __align__(16) float Vs[32][64];
    float qreg[32], o[32];
    const float4* qp = (const float4*)(g_q + ((size_t)qpos * NHEAD + qh) * HDIM + half * 32);
#pragma unroll
    for (int d4 = 0; d4 < 8; d4++) {
        float4 v = qp[d4];
        qreg[4 * d4] = v.x * 0.125f; qreg[4 * d4 + 1] = v.y * 0.125f;
        qreg[4 * d4 + 2] = v.z * 0.125f; qreg[4 * d4 + 3] = v.w * 0.125f;
        o[4 * d4] = 0.f; o[4 * d4 + 1] = 0.f; o[4 * d4 + 2] = 0.f; o[4 * d4 + 3] = 0.f;
    }
    float m = -INFINITY, lsum = 0.f;
    int kend = bq * 32 + 32;
    int qmax_w = bq * 32 + (w & 1) * 16 + 15;
    for (int kt = 0; kt < kend; kt += 32) {
        for (int i = tid; i < 32 * 16; i += 256) {
            int j = i >> 4, d4 = (i & 15) * 4;
            *(float4*)&Ks[j][d4] = *(const float4*)(g_k + ((size_t)(kt + j) * NKV + kvh) * HDIM + d4);
            *(float4*)&Vs[j][d4] = *(const float4*)(g_v + ((size_t)(kt + j) * NKV + kvh) * HDIM + d4);
        }
        __syncthreads();
        int jw = qmax_w - kt + 1;
        if (jw > 32) jw = 32;
        for (int j = 0; j < jw; j += 4) {
            float s0 = 0.f, s1 = 0.f, s2 = 0.f, s3 = 0.f;
            int hb = half * 32;
#pragma unroll
            for (int d = 0; d < 32; d += 4) {
                float4 k0 = *(const float4*)&Ks[j][hb + d];
                float4 k1 = *(const float4*)&Ks[j + 1][hb + d];
                float4 k2 = *(const float4*)&Ks[j + 2][hb + d];
                float4 k3 = *(const float4*)&Ks[j + 3][hb + d];
                s0 += qreg[d] * k0.x + qreg[d + 1] * k0.y + qreg[d + 2] * k0.z + qreg[d + 3] * k0.w;
                s1 += qreg[d] * k1.x + qreg[d + 1] * k1.y + qreg[d + 2] * k1.z + qreg[d + 3] * k1.w;
                s2 += qreg[d] * k2.x + qreg[d + 1] * k2.y + qreg[d + 2] * k2.z + qreg[d + 3] * k2.w;
                s3 += qreg[d] * k3.x + qreg[d + 1] * k3.y + qreg[d + 2] * k3.z + qreg[d + 3] * k3.w;
            }
            s0 += __shfl_xor_sync(0xFFFFFFFFu, s0, 16);
            s1 += __shfl_xor_sync(0xFFFFFFFFu, s1, 16);
            s2 += __shfl_xor_sync(0xFFFFFFFFu, s2, 16);
            s3 += __shfl_xor_sync(0xFFFFFFFFu, s3, 16);
            if (kt + j     > qpos) s0 = -1e30f;
            if (kt + j + 1 > qpos) s1 = -1e30f;
            if (kt + j + 2 > qpos) s2 = -1e30f;
            if (kt + j + 3 > qpos) s3 = -1e30f;
            float mn = fmaxf(fmaxf(fmaxf(s0, s1), fmaxf(s2, s3)), m);
            float corr = __expf(m - mn);
            float p0 = __expf(s0 - mn), p1 = __expf(s1 - mn);
            float p2 = __expf(s2 - mn), p3 = __expf(s3 - mn);
            lsum = lsum * corr + p0 + p1 + p2 + p3;
            m = mn;
#pragma unroll
            for (int d = 0; d < 32; d += 4) {
                float4 v0 = *(const float4*)&Vs[j][hb + d];
                float4 v1 = *(const float4*)&Vs[j + 1][hb + d];
                float4 v2 = *(const float4*)&Vs[j + 2][hb + d];
                float4 v3 = *(const float4*)&Vs[j + 3][hb + d];
                o[d]     = o[d]     * corr + p0 * v0.x + p1 * v1.x + p2 * v2.x + p3 * v3.x;
                o[d + 1] = o[d + 1] * corr + p0 * v0.y + p1 * v1.y + p2 * v2.y + p3 * v3.y;
                o[d + 2] = o[d + 2] * corr + p0 * v0.z + p1 * v1.z + p2 * v2.z + p3 * v3.z;
                o[d + 3] = o[d + 3] * corr + p0 * v0.w + p1 * v1.w + p2 * v2.w + p3 * v3.w;
            }
        }
        __syncthreads();
    }
    float invl = 1.f / lsum;
    size_t base = (size_t)qpos * DMODEL + (size_t)qh * HDIM + half * 32;
#pragma unroll
    for (int d = 0; d < 32; d++) {
        float val = o[d] * invl;
        bf16 h, lo;
        bfsplit(val, h, lo);
        g_at_hi[base + d] = h;
        g_at_lo[base + d] = lo;
    }
}

__global__ __launch_bounds__(128) void router_kernel(
    const float* __restrict__ T, const float* __restrict__ Wr)
{
    int t = blockIdx.x;
    __shared__ float sred[128 * 8];
    float acc[8] = {};
    const float* tr = T + (size_t)t * DMODEL;
    for (int d = threadIdx.x; d < DMODEL; d += 128) {
        float x = tr[d];
        const float* wr = Wr + (size_t)d * NEXP;
#pragma unroll
        for (int e = 0; e < 8; e++) acc[e] += x * wr[e];
    }
#pragma unroll
    for (int e = 0; e < 8; e++) sred[threadIdx.x * 8 + e] = acc[e];
    __syncthreads();
    for (int s = 64; s > 0; s >>= 1) {
        if (threadIdx.x < s) {
#pragma unroll
            for (int e = 0; e < 8; e++)
                sred[threadIdx.x * 8 + e] += sred[(threadIdx.x + s) * 8 + e];
        }
        __syncthreads();
    }
    if (threadIdx.x == 0) {
        float best = -1e30f, second = -1e30f;
        int bi = 0, si = 0;
#pragma unroll
        for (int e = 0; e < 8; e++) {
            float v = sred[e];
            if (v > best)        { second = best; si = bi; best = v; bi = e; }
            else if (v > second) { second = v; si = e; }
        }
        float p0 = 1.f / (1.f + expf(second - best));
        g_topi[2 * t] = bi;  g_topi[2 * t + 1] = si;
        g_topw[2 * t] = p0;  g_topw[2 * t + 1] = 1.f - p0;
    }
}

__global__ __launch_bounds__(256) void assign_kernel()
{
    __shared__ int cnt[NEXP], base[NEXP + 1], cur[NEXP];
    if (threadIdx.x < NEXP) cnt[threadIdx.x] = 0;
    __syncthreads();
    for (int t = threadIdx.x; t < NTOK; t += 256) {
        atomicAdd(&cnt[g_topi[2 * t]], 1);
        atomicAdd(&cnt[g_topi[2 * t + 1]], 1);
    }
    __syncthreads();
    if (threadIdx.x == 0) {
        int s = 0;
        for (int e = 0; e < NEXP; e++) { base[e] = s; s += cnt[e]; }
        base[NEXP] = s;
    }
    __syncthreads();
    if (threadIdx.x < NEXP) cur[threadIdx.x] = base[threadIdx.x];
    if (threadIdx.x < NEXP + 1) g_off[threadIdx.x] = base[threadIdx.x];
    __syncthreads();
    for (int t = threadIdx.x; t < NTOK; t += 256) {
#pragma unroll
        for (int k = 0; k < 2; k++) {
            int e = g_topi[2 * t + k];
            int slot = atomicAdd(&cur[e], 1);
            g_slot_token[slot] = t;
            g_slot_of[2 * t + k] = slot;
        }
    }
}

__global__ __launch_bounds__(512) void silu_kernel()
{
    size_t i = ((size_t)blockIdx.x * 512 + threadIdx.x) * 4;
    float4 g = *(const float4*)(g_gate + i);
    float4 u = *(const float4*)(g_up + i);
    float a0 = g.x / (1.f + __expf(-g.x)) * u.x;
    float a1 = g.y / (1.f + __expf(-g.y)) * u.y;
    float a2 = g.z / (1.f + __expf(-g.z)) * u.z;
    float a3 = g.w / (1.f + __expf(-g.w)) * u.w;
    bf16 h0, l0, h1, l1, h2, l2, h3, l3;
    bfsplit(a0, h0, l0); bfsplit(a1, h1, l1);
    bfsplit(a2, h2, l2); bfsplit(a3, h3, l3);
    bf16* ph = g_act_hi + i;
    bf16* pl = g_act_lo + i;
    ph[0] = h0; ph[1] = h1; ph[2] = h2; ph[3] = h3;
    pl[0] = l0; pl[1] = l1; pl[2] = l2; pl[3] = l3;
}

__global__ __launch_bounds__(256) void combine_kernel(
    const float* __restrict__ h2, float* __restrict__ out)
{
    int t = blockIdx.x;
    int s0 = g_slot_of[2 * t], s1 = g_slot_of[2 * t + 1];
    float w0 = g_topw[2 * t], w1 = g_topw[2 * t + 1];
    const float* d0 = g_down + (size_t)s0 * DMODEL;
    const float* d1 = g_down + (size_t)s1 * DMODEL;
    const float* hr = h2 + (size_t)t * DMODEL;
    float* orow = out + (size_t)t * DMODEL;
    for (int d = threadIdx.x; d < DMODEL; d += 256)
        orow[d] = hr[d] + w0 * d0[d] + w1 * d1[d];
}

// ======================= launch =======================
extern "C" void kernel_launch(void* const* d_in, const int* in_sizes, int n_in,
                              void* d_out, int out_size)
{
    const float* hs   = (const float*)d_in[0];
    const int*   pos  = (const int*)d_in[1];
    const float* ln1w = (const float*)d_in[2];
    const float* Wq   = (const float*)d_in[3];
    const float* Wk   = (const float*)d_in[4];
    const float* Wv   = (const float*)d_in[5];
    const float* Wo   = (const float*)d_in[6];
    const float* ln2w = (const float*)d_in[7];
    const float* Wr   = (const float*)d_in[8];
    const float* W1   = (const float*)d_in[9];
    const float* W3   = (const float*)d_in[10];
    const float* W2   = (const float*)d_in[11];
    float* out = (float*)d_out;

    cudaFuncSetAttribute(tc_gemm, cudaFuncAttributeMaxDynamicSharedMemorySize, GEMM_SMEM);
    cudaFuncSetAttribute(tc_gemm_kv, cudaFuncAttributeMaxDynamicSharedMemorySize, GEMM_SMEM);

    void* p;
    cudaGetSymbolAddress(&p, g_hn_hi);  bf16* hn_hi = (bf16*)p;
    cudaGetSymbolAddress(&p, g_hn_lo);  bf16* hn_lo = (bf16*)p;
    cudaGetSymbolAddress(&p, g_q);      float* q    = (float*)p;
    cudaGetSymbolAddress(&p, g_at_hi);  bf16* at_hi = (bf16*)p;
    cudaGetSymbolAddress(&p, g_at_lo);  bf16* at_lo = (bf16*)p;
    cudaGetSymbolAddress(&p, g_h2);     float* h2   = (float*)p;
    cudaGetSymbolAddress(&p, g_tn);     float* tn   = (float*)p;
    cudaGetSymbolAddress(&p, g_tn_hi);  bf16* tn_hi = (bf16*)p;
    cudaGetSymbolAddress(&p, g_tn_lo);  bf16* tn_lo = (bf16*)p;
    cudaGetSymbolAddress(&p, g_gate);   float* gate = (float*)p;
    cudaGetSymbolAddress(&p, g_up);     float* up   = (float*)p;
    cudaGetSymbolAddress(&p, g_act_hi); bf16* ac_hi = (bf16*)p;
    cudaGetSymbolAddress(&p, g_act_lo); bf16* ac_lo = (bf16*)p;
    cudaGetSymbolAddress(&p, g_down);   float* down = (float*)p;

    // 1. rmsnorm1 -> bf16 hi/lo
    rmsnorm_kernel<<<NTOK, 256>>>(hs, ln1w, nullptr, hn_hi, hn_lo);
    // 2. Q projection + merged K/V projection
    tc_gemm<<<dim3(32, 16, 1), 256, GEMM_SMEM>>>(hn_hi, hn_lo, Wq, q, nullptr, NTOK, 2048, DMODEL, 0, 0);
    tc_gemm_kv<<<dim3(16, 16, 1), 256, GEMM_SMEM>>>(hn_hi, hn_lo, Wk, Wv);
    // 3. RoPE (q + k in one launch)
    rope_all_kernel<<<SEQ, 256>>>(pos);
    // 4. flash attention -> attn hi/lo
    flash_kernel<<<dim3(SEQ / 32, NKV), 256>>>();
    // 5. O projection + residual
    tc_gemm<<<dim3(32, 16, 1), 256, GEMM_SMEM>>>(at_hi, at_lo, Wo, h2, hs, NTOK, 2048, DMODEL, 0, 0);
    // 6. rmsnorm2
    rmsnorm_kernel<<<NTOK, 256>>>(h2, ln2w, tn, tn_hi, tn_lo);
    // 7-8. router + assignment
    router_kernel<<<NTOK, 128>>>(tn, Wr);
    assign_kernel<<<1, 256>>>();
    // 9. gate & up grouped GEMMs (gather)
    tc_gemm<<<dim3(112, 16, 8), 256, GEMM_SMEM>>>(tn_hi, tn_lo, W1, gate, nullptr, 0, FDIM, DMODEL, 1, 1);
    tc_gemm<<<dim3(112, 16, 8), 256, GEMM_SMEM>>>(tn_hi, tn_lo, W3, up, nullptr, 0, FDIM, DMODEL, 1, 1);
    // 10. silu(gate)*up -> act hi/lo
    silu_kernel<<<(int)((size_t)NSLOT * FDIM / 4 / 512), 512>>>();
    // 11. down grouped GEMM (slot-space A)
    tc_gemm<<<dim3(32, 16, 8), 256, GEMM_SMEM>>>(ac_hi, ac_lo, W2, down, nullptr, 0, DMODEL, FDIM, 1, 0);
    // 12. combine with residual
    combine_kernel<<<NTOK, 256>>>(h2, out);
}